// round 1
// baseline (speedup 1.0000x reference)
#include <cuda_runtime.h>
#include <math.h>

#define B_  8
#define T_  2048
#define C_  1024
#define NF_ 64
#define M_  (B_*T_)      /* 16384 rows */
#define TNF 128          /* 2*NF */

// ---------------- scratch (device globals; no allocation) ----------------
__device__ float    g_q[(size_t)M_ * C_];     // 64 MB
__device__ float    g_v[(size_t)M_ * C_];     // 64 MB
__device__ float    g_G[(size_t)M_ * TNF];    // 8 MB
__device__ float    g_Wcat[C_ * TNF];         // 512 KB: [Wtop | Wbot]
__device__ float    g_idG[NF_];               // identity @ Wtop
__device__ unsigned g_rowmax[M_];             // per-row max |z2| (float bits)

enum { MODE_SPLIT = 0, MODE_PLAIN = 1, MODE_PROJ = 2 };

// ---------------- generic tiled fp32 GEMM ----------------
// C = A @ B (+bias); MODE_SPLIT: split columns into g_q / g_v
// MODE_PROJ: A element fused as A*A2 (q*v)
template<int BM, int BN, int TM, int TN, int MODE>
__global__ __launch_bounds__(256)
void gemm_k(const float* __restrict__ A, const float* __restrict__ A2,
            const float* __restrict__ Bmat, const float* __restrict__ bias,
            float* __restrict__ Cmat, int M, int N, int K)
{
    constexpr int BK = 16;
    __shared__ float As[BK][BM + 4];
    __shared__ float Bs[BK][BN + 4];

    const int tid = threadIdx.x;
    const int bm  = blockIdx.y * BM;
    const int bn  = blockIdx.x * BN;
    constexpr int TC = BN / TN;          // threads along N
    const int tx = tid % TC;
    const int ty = tid / TC;

    float acc[TM][TN];
#pragma unroll
    for (int i = 0; i < TM; i++)
#pragma unroll
        for (int j = 0; j < TN; j++) acc[i][j] = 0.f;

    constexpr int A4 = (BM * BK) / (256 * 4);
    constexpr int B4 = (BK * BN) / (256 * 4);

    for (int k0 = 0; k0 < K; k0 += BK) {
#pragma unroll
        for (int i = 0; i < A4; i++) {
            int idx = (tid + i * 256) * 4;
            int r = idx / BK, c = idx % BK;
            float4 va = *(const float4*)&A[(size_t)(bm + r) * K + k0 + c];
            if (MODE == MODE_PROJ) {
                float4 vb = *(const float4*)&A2[(size_t)(bm + r) * K + k0 + c];
                va.x *= vb.x; va.y *= vb.y; va.z *= vb.z; va.w *= vb.w;
            }
            As[c + 0][r] = va.x; As[c + 1][r] = va.y;
            As[c + 2][r] = va.z; As[c + 3][r] = va.w;
        }
#pragma unroll
        for (int i = 0; i < B4; i++) {
            int idx = (tid + i * 256) * 4;
            int r = idx / BN, c = idx % BN;
            *(float4*)&Bs[r][c] = *(const float4*)&Bmat[(size_t)(k0 + r) * N + bn + c];
        }
        __syncthreads();

#pragma unroll
        for (int k = 0; k < BK; k++) {
            float a[TM], b[TN];
#pragma unroll
            for (int i = 0; i < TM; i++) a[i] = As[k][ty * TM + i];
#pragma unroll
            for (int j = 0; j < TN; j++) b[j] = Bs[k][tx * TN + j];
#pragma unroll
            for (int i = 0; i < TM; i++)
#pragma unroll
                for (int j = 0; j < TN; j++)
                    acc[i][j] = fmaf(a[i], b[j], acc[i][j]);
        }
        __syncthreads();
    }

#pragma unroll
    for (int i = 0; i < TM; i++) {
        int row = bm + ty * TM + i;
#pragma unroll
        for (int j = 0; j < TN; j++) {
            int col = bn + tx * TN + j;
            float v = acc[i][j];
            if (MODE == MODE_SPLIT) {
                v += bias[col];
                if (col < C_) g_q[(size_t)row * C_ + col] = v;
                else          g_v[(size_t)row * C_ + (col - C_)] = v;
            } else if (MODE == MODE_PLAIN) {
                Cmat[(size_t)row * N + col] = v;
            } else {
                Cmat[(size_t)row * N + col] = v + bias[col];
            }
        }
    }
}

// ---------------- weight repack + identity projection ----------------
__global__ void pack_wcat_k(const float* __restrict__ freqW)
{
    int idx = blockIdx.x * 256 + threadIdx.x;      // < 1024*128
    int k = idx >> 7, j = idx & 127;
    g_Wcat[idx] = (j < 64) ? freqW[k * 64 + j]
                           : freqW[(k + 1024) * 64 + (j - 64)];
}

__global__ void idg_k(const float* __restrict__ freqW, const float* __restrict__ identity)
{
    int j = threadIdx.x;   // 64 threads
    float s = 0.f;
    for (int k = 0; k < 1024; k++) s = fmaf(identity[k], freqW[k * 64 + j], s);
    g_idG[j] = s;
}

__global__ void reset_k() { g_rowmax[blockIdx.x * 256 + threadIdx.x] = 0u; }

// ---------------- fused scan step: shift + sin/cos + (sc @ out_W) + rowmax ----------------
// Each block: 64 rows x 128 cols of the (16384 x 1024) output.
// sc tile built in smem from G (with shift n); out_W read from global (L2-hot).
__global__ __launch_bounds__(256)
void scan_out_k(const float* __restrict__ outW, const float* __restrict__ freq_b,
                const float* __restrict__ out_b, int n)
{
    constexpr int BM = 64, BN = 128;
    __shared__ float As[TNF][BM + 4];   // [k][row], ~34.8 KB

    const int tid = threadIdx.x;
    const int bm = blockIdx.y * BM;
    const int bn = blockIdx.x * BN;

    // phase 1: build sin/cos tile
    {
        int j = tid & 63;
        float fb = freq_b[j];
#pragma unroll
        for (int r = tid >> 6; r < BM; r += 4) {
            int row = bm + r;
            int t = row & (T_ - 1);
            float g1 = (t >= n) ? g_G[(size_t)(row - n) * TNF + j] : g_idG[j];
            float f = g1 + g_G[(size_t)row * TNF + 64 + j] + fb;
            float s, c;
            sincosf(f, &s, &c);
            As[j][r]      = s;
            As[64 + j][r] = c;
        }
    }
    __syncthreads();

    // phase 2: 64x128 GEMM, K=128; micro tile 4x8; out_W streamed (broadcast across ty)
    const int tx = tid & 15, ty = tid >> 4;
    float acc[4][8];
#pragma unroll
    for (int i = 0; i < 4; i++)
#pragma unroll
        for (int j = 0; j < 8; j++) acc[i][j] = 0.f;

    const float* Bp = &outW[bn + tx * 8];
#pragma unroll 4
    for (int k = 0; k < 128; k++) {
        float4 a4 = *(const float4*)&As[k][ty * 4];
        float4 b0 = *(const float4*)&Bp[(size_t)k * C_];
        float4 b1 = *(const float4*)&Bp[(size_t)k * C_ + 4];
        float a[4] = {a4.x, a4.y, a4.z, a4.w};
        float b[8] = {b0.x, b0.y, b0.z, b0.w, b1.x, b1.y, b1.z, b1.w};
#pragma unroll
        for (int i = 0; i < 4; i++)
#pragma unroll
            for (int j = 0; j < 8; j++)
                acc[i][j] = fmaf(a[i], b[j], acc[i][j]);
    }

    // epilogue: + out_b, row |max| reduce across 16 lanes, write unnormalized q
    const int row0 = bm + ty * 4;
    const int col0 = bn + tx * 8;
    float ob[8];
#pragma unroll
    for (int j = 0; j < 8; j++) ob[j] = out_b[col0 + j];

#pragma unroll
    for (int i = 0; i < 4; i++) {
        float m = 0.f;
#pragma unroll
        for (int j = 0; j < 8; j++) {
            acc[i][j] += ob[j];
            m = fmaxf(m, fabsf(acc[i][j]));
        }
#pragma unroll
        for (int off = 8; off; off >>= 1)
            m = fmaxf(m, __shfl_xor_sync(0xffffffffu, m, off, 16));
        if (tx == 0) atomicMax(&g_rowmax[row0 + i], __float_as_uint(m));

        float* qp = &g_q[(size_t)(row0 + i) * C_ + col0];
        *(float4*)qp       = make_float4(acc[i][0], acc[i][1], acc[i][2], acc[i][3]);
        *(float4*)(qp + 4) = make_float4(acc[i][4], acc[i][5], acc[i][6], acc[i][7]);
    }
}

// ---------------- normalize: q /= (rowmax + eps) ----------------
__global__ __launch_bounds__(256)
void norm_k()
{
    size_t idx = (size_t)blockIdx.x * blockDim.x + threadIdx.x;  // over M*C/4
    int row = (int)(idx >> 8);                                    // (idx*4)/1024
    float m = __uint_as_float(g_rowmax[row]);
    float s = 1.f / (m + 1e-6f);
    float4 v = *(float4*)&g_q[idx * 4];
    v.x *= s; v.y *= s; v.z *= s; v.w *= s;
    *(float4*)&g_q[idx * 4] = v;
}

// ---------------- launch ----------------
extern "C" void kernel_launch(void* const* d_in, const int* in_sizes, int n_in,
                              void* d_out, int out_size)
{
    (void)in_sizes; (void)n_in; (void)out_size;
    const float* x       = (const float*)d_in[0];
    const float* attn_W  = (const float*)d_in[1];
    const float* attn_b  = (const float*)d_in[2];
    const float* freq_W  = (const float*)d_in[3];
    const float* freq_b  = (const float*)d_in[4];
    const float* out_W   = (const float*)d_in[5];
    const float* out_b   = (const float*)d_in[6];
    const float* proj_W  = (const float*)d_in[7];
    const float* proj_b  = (const float*)d_in[8];
    const float* identity= (const float*)d_in[9];
    float* out = (float*)d_out;

    float *qp, *vp, *Gp, *Wcatp;
    cudaGetSymbolAddress((void**)&qp,    g_q);
    cudaGetSymbolAddress((void**)&vp,    g_v);
    cudaGetSymbolAddress((void**)&Gp,    g_G);
    cudaGetSymbolAddress((void**)&Wcatp, g_Wcat);

    // weight repack + identity projection
    pack_wcat_k<<<512, 256>>>(freq_W);
    idg_k<<<1, 64>>>(freq_W, identity);

    // qv = x @ attn_W + attn_b  ->  split into g_q (cols<1024) and g_v
    gemm_k<128, 128, 8, 8, MODE_SPLIT>
        <<<dim3(2048 / 128, M_ / 128), 256>>>(x, nullptr, attn_W, attn_b, nullptr,
                                              M_, 2048, C_);

    // log-scan: 11 iterations
    for (int n = 1; n < T_; n <<= 1) {
        // G = q @ [Wtop | Wbot]   (16384 x 1024 x 128)
        gemm_k<64, 128, 4, 8, MODE_PLAIN>
            <<<dim3(1, M_ / 64), 256>>>(qp, nullptr, Wcatp, nullptr, Gp,
                                        M_, TNF, C_);
        reset_k<<<M_ / 256, 256>>>();
        // fused shift + sin/cos + (sc @ out_W + out_b) + rowmax; writes unnormalized q
        scan_out_k<<<dim3(C_ / 128, M_ / 64), 256>>>(out_W, freq_b, out_b, n);
        // q /= (rowmax + eps)
        norm_k<<<(M_ * (C_ / 4)) / 256, 256>>>();
    }

    // out = (q*v) @ proj_W + proj_b
    gemm_k<128, 128, 8, 8, MODE_PROJ>
        <<<dim3(C_ / 128, M_ / 128), 256>>>(qp, vp, proj_W, proj_b, out,
                                            M_, C_, C_);
}

// round 2
// speedup vs baseline: 4.4697x; 4.4697x over previous
#include <cuda_runtime.h>
#include <math.h>
#include <stdint.h>

#define B_  8
#define T_  2048
#define C_  1024
#define NF_ 64
#define M_  (B_*T_)      /* 16384 rows */
#define TNF 128          /* 2*NF */

// ---------------- scratch (device globals; no allocation) ----------------
__device__ float    g_q[(size_t)M_ * C_];     // 64 MB  (UNNORMALIZED q)
__device__ float    g_v[(size_t)M_ * C_];     // 64 MB
__device__ float    g_G[(size_t)M_ * TNF];    // 8 MB   (G_un = q_un @ Wcat)
__device__ float    g_SC[(size_t)M_ * TNF];   // 8 MB   ([sin|cos] matrix)
__device__ float    g_Wcat[C_ * TNF];         // 512 KB [Wtop | Wbot]
__device__ float    g_idG[NF_];               // identity @ Wtop
__device__ unsigned g_rm[2][M_];              // per-row |max| bits, ping-pong

enum { MODE_SPLIT = 0, MODE_PLAIN = 1, MODE_SCAN = 2, MODE_PROJ = 3 };

__device__ __forceinline__ uint32_t f2tf(float f) {
    uint32_t u; asm("cvt.rna.tf32.f32 %0, %1;" : "=r"(u) : "f"(f)); return u;
}
__device__ __forceinline__ void mma8(float* c, const uint32_t* a, const uint32_t* b) {
    asm volatile(
        "mma.sync.aligned.m16n8k8.row.col.f32.tf32.tf32.f32 "
        "{%0,%1,%2,%3},{%4,%5,%6,%7},{%8,%9},{%0,%1,%2,%3};\n"
        : "+f"(c[0]), "+f"(c[1]), "+f"(c[2]), "+f"(c[3])
        : "r"(a[0]), "r"(a[1]), "r"(a[2]), "r"(a[3]), "r"(b[0]), "r"(b[1]));
}

// ---------------- generic tf32 tensor-core GEMM ----------------
// BN=128, BK=32 fixed. 256 threads = 8 warps, (BM/WM) x (128/WN) warp grid.
// MODE_SPLIT: +bias, cols<1024 -> g_q else g_v
// MODE_PLAIN: plain store
// MODE_SCAN : +bias, store q_un, atomicMax row |max| into rmw
// MODE_PROJ : A element = A * A2 * s[row] (s from rma), +bias
template<int BM, int WM, int WN, int MODE>
__global__ __launch_bounds__(256)
void gemm_tc(const float* __restrict__ A, const float* __restrict__ A2,
             const float* __restrict__ Bm, const float* __restrict__ bias,
             float* __restrict__ Cmat,
             const unsigned* __restrict__ rma, unsigned* __restrict__ rmw,
             int N, int K)
{
    constexpr int BN = 128, BK = 32;
    constexpr int WARPS_N = BN / WN;
    constexpr int MT = WM / 16, NT = WN / 8;

    __shared__ uint32_t As[BM][BK + 4];   // stride 36: banks 4g+t conflict-free
    __shared__ uint32_t Bs[BK][BN + 8];   // stride 136: banks 8t+g conflict-free

    const int tid  = threadIdx.x;
    const int bm   = blockIdx.y * BM;
    const int bn   = blockIdx.x * BN;
    const int warp = tid >> 5, lane = tid & 31;
    const int grp  = lane >> 2, tig = lane & 3;
    const int wm   = warp / WARPS_N, wn = warp % WARPS_N;

    float acc[MT][NT][4];
#pragma unroll
    for (int i = 0; i < MT; i++)
#pragma unroll
        for (int j = 0; j < NT; j++)
#pragma unroll
            for (int r = 0; r < 4; r++) acc[i][j][r] = 0.f;

    const int lr = tid >> 3;          // A loader: row 0..31 (+32*i)
    const int lc = (tid & 7) * 4;     // A loader: col
    const int kr = tid >> 5;          // B loader: k-row 0..7 (+8*i)
    const int kc = (tid & 31) * 4;    // B loader: col

    for (int k0 = 0; k0 < K; k0 += BK) {
        // stage A (with tf32 convert; PROJ fuses q*v*s)
#pragma unroll
        for (int i = 0; i < BM / 32; i++) {
            int r = lr + i * 32;
            float4 a4 = *(const float4*)&A[(size_t)(bm + r) * K + k0 + lc];
            if (MODE == MODE_PROJ) {
                float4 v4 = *(const float4*)&A2[(size_t)(bm + r) * K + k0 + lc];
                float s = 1.f / (__uint_as_float(rma[bm + r]) + 1e-6f);
                a4.x *= v4.x * s; a4.y *= v4.y * s;
                a4.z *= v4.z * s; a4.w *= v4.w * s;
            }
            uint4 u = make_uint4(f2tf(a4.x), f2tf(a4.y), f2tf(a4.z), f2tf(a4.w));
            *(uint4*)&As[r][lc] = u;
        }
        // stage B
#pragma unroll
        for (int i = 0; i < 4; i++) {
            int kk = kr + i * 8;
            float4 b4 = *(const float4*)&Bm[(size_t)(k0 + kk) * N + bn + kc];
            uint4 u = make_uint4(f2tf(b4.x), f2tf(b4.y), f2tf(b4.z), f2tf(b4.w));
            *(uint4*)&Bs[kk][kc] = u;
        }
        __syncthreads();

#pragma unroll
        for (int ks = 0; ks < 4; ks++) {
            const int kk = ks * 8;
            uint32_t af[MT][4], bf[NT][2];
#pragma unroll
            for (int mt = 0; mt < MT; mt++) {
                int r = wm * WM + mt * 16 + grp;
                af[mt][0] = As[r    ][kk + tig];
                af[mt][1] = As[r + 8][kk + tig];
                af[mt][2] = As[r    ][kk + tig + 4];
                af[mt][3] = As[r + 8][kk + tig + 4];
            }
#pragma unroll
            for (int nt = 0; nt < NT; nt++) {
                int cc = wn * WN + nt * 8 + grp;
                bf[nt][0] = Bs[kk + tig    ][cc];
                bf[nt][1] = Bs[kk + tig + 4][cc];
            }
#pragma unroll
            for (int mt = 0; mt < MT; mt++)
#pragma unroll
                for (int nt = 0; nt < NT; nt++)
                    mma8(acc[mt][nt], af[mt], bf[nt]);
        }
        __syncthreads();
    }

    // ---------------- epilogue ----------------
#pragma unroll
    for (int mt = 0; mt < MT; mt++) {
        int row0 = bm + wm * WM + mt * 16 + grp;   // and row0+8
        float mx0 = 0.f, mx1 = 0.f;
#pragma unroll
        for (int nt = 0; nt < NT; nt++) {
            int col = bn + wn * WN + nt * 8 + tig * 2;
            float v0 = acc[mt][nt][0], v1 = acc[mt][nt][1];
            float v2 = acc[mt][nt][2], v3 = acc[mt][nt][3];
            if (MODE != MODE_PLAIN) {
                float b0 = bias[col], b1 = bias[col + 1];
                v0 += b0; v1 += b1; v2 += b0; v3 += b1;
            }
            if (MODE == MODE_SPLIT) {
                if (col < C_) {
                    *(float2*)&g_q[(size_t)row0 * C_ + col]       = make_float2(v0, v1);
                    *(float2*)&g_q[(size_t)(row0 + 8) * C_ + col] = make_float2(v2, v3);
                } else {
                    *(float2*)&g_v[(size_t)row0 * C_ + col - C_]       = make_float2(v0, v1);
                    *(float2*)&g_v[(size_t)(row0 + 8) * C_ + col - C_] = make_float2(v2, v3);
                }
            } else if (MODE == MODE_SCAN) {
                *(float2*)&g_q[(size_t)row0 * C_ + col]       = make_float2(v0, v1);
                *(float2*)&g_q[(size_t)(row0 + 8) * C_ + col] = make_float2(v2, v3);
                mx0 = fmaxf(mx0, fmaxf(fabsf(v0), fabsf(v1)));
                mx1 = fmaxf(mx1, fmaxf(fabsf(v2), fabsf(v3)));
            } else {
                *(float2*)&Cmat[(size_t)row0 * N + col]       = make_float2(v0, v1);
                *(float2*)&Cmat[(size_t)(row0 + 8) * N + col] = make_float2(v2, v3);
            }
        }
        if (MODE == MODE_SCAN) {
            // reduce over the 4 lanes (tig) sharing each row, then one atomic
#pragma unroll
            for (int off = 1; off < 4; off <<= 1) {
                mx0 = fmaxf(mx0, __shfl_xor_sync(0xffffffffu, mx0, off));
                mx1 = fmaxf(mx1, __shfl_xor_sync(0xffffffffu, mx1, off));
            }
            if (tig == 0) {
                atomicMax(&rmw[row0],     __float_as_uint(mx0));
                atomicMax(&rmw[row0 + 8], __float_as_uint(mx1));
            }
        }
    }
}

// ---------------- small kernels ----------------
__global__ void pack_wcat_k(const float* __restrict__ freqW)
{
    int idx = blockIdx.x * 256 + threadIdx.x;      // < 1024*128
    int k = idx >> 7, j = idx & 127;
    g_Wcat[idx] = (j < 64) ? freqW[k * 64 + j]
                           : freqW[(k + 1024) * 64 + (j - 64)];
}

__global__ void idg_k(const float* __restrict__ freqW, const float* __restrict__ identity)
{
    int j = threadIdx.x;   // 64 threads
    float s = 0.f;
    for (int k = 0; k < 1024; k++) s = fmaf(identity[k], freqW[k * 64 + j], s);
    g_idG[j] = s;
}

__global__ void init_rm_k()   // scale == 1 for first iteration
{
    g_rm[0][blockIdx.x * 256 + threadIdx.x] = __float_as_uint(1.0f - 1e-6f);
}

// shift + per-row scale + sin/cos -> g_SC ; also zeroes rmnext
__global__ __launch_bounds__(256)
void sc_k(const float* __restrict__ freq_b, int n,
          const unsigned* __restrict__ rmprev, unsigned* __restrict__ rmnext)
{
    int idx = blockIdx.x * 256 + threadIdx.x;      // < M*64
    int row = idx >> 6, j = idx & 63;
    if (j == 0) rmnext[row] = 0u;
    int t = row & (T_ - 1);
    float sown = 1.f / (__uint_as_float(rmprev[row]) + 1e-6f);
    float g2 = g_G[(size_t)row * TNF + 64 + j] * sown;
    float g1;
    if (t >= n) {
        float sp = 1.f / (__uint_as_float(rmprev[row - n]) + 1e-6f);
        g1 = g_G[(size_t)(row - n) * TNF + j] * sp;
    } else {
        g1 = g_idG[j];
    }
    float f = g1 + g2 + freq_b[j];
    float s, c;
    sincosf(f, &s, &c);
    g_SC[(size_t)row * TNF + j]      = s;
    g_SC[(size_t)row * TNF + 64 + j] = c;
}

// ---------------- launch ----------------
extern "C" void kernel_launch(void* const* d_in, const int* in_sizes, int n_in,
                              void* d_out, int out_size)
{
    (void)in_sizes; (void)n_in; (void)out_size;
    const float* x        = (const float*)d_in[0];
    const float* attn_W   = (const float*)d_in[1];
    const float* attn_b   = (const float*)d_in[2];
    const float* freq_W   = (const float*)d_in[3];
    const float* freq_b   = (const float*)d_in[4];
    const float* out_W    = (const float*)d_in[5];
    const float* out_b    = (const float*)d_in[6];
    const float* proj_W   = (const float*)d_in[7];
    const float* proj_b   = (const float*)d_in[8];
    const float* identity = (const float*)d_in[9];
    float* out = (float*)d_out;

    float *qp, *vp, *Gp, *SCp, *Wcatp;
    unsigned* rmp;
    cudaGetSymbolAddress((void**)&qp,    g_q);
    cudaGetSymbolAddress((void**)&vp,    g_v);
    cudaGetSymbolAddress((void**)&Gp,    g_G);
    cudaGetSymbolAddress((void**)&SCp,   g_SC);
    cudaGetSymbolAddress((void**)&Wcatp, g_Wcat);
    cudaGetSymbolAddress((void**)&rmp,   g_rm);

    pack_wcat_k<<<512, 256>>>(freq_W);
    idg_k<<<1, 64>>>(freq_W, identity);
    init_rm_k<<<M_ / 256, 256>>>();

    // qv = x @ attn_W + attn_b -> split into g_q / g_v   (16384x2048x1024)
    gemm_tc<128, 32, 64, MODE_SPLIT>
        <<<dim3(2048 / 128, M_ / 128), 256>>>(x, nullptr, attn_W, attn_b, nullptr,
                                              nullptr, nullptr, 2048, 1024);

    unsigned* rprev = rmp;          // g_rm[0]
    unsigned* rnext = rmp + M_;     // g_rm[1]

    for (int n = 1; n < T_; n <<= 1) {
        // G_un = q_un @ Wcat   (16384x128x1024)
        gemm_tc<64, 32, 32, MODE_PLAIN>
            <<<dim3(1, M_ / 64), 256>>>(qp, nullptr, Wcatp, nullptr, Gp,
                                        nullptr, nullptr, TNF, 1024);
        // SC = [sin f | cos f],  f = s[r-n]*G[r-n,:64] (or idG) + s[r]*G[r,64:] + fb
        sc_k<<<(M_ * 64) / 256, 256>>>(freq_b, n, rprev, rnext);
        // q_un = SC @ out_W + out_b ; rowmax -> rnext   (16384x1024x128)
        gemm_tc<128, 32, 64, MODE_SCAN>
            <<<dim3(C_ / 128, M_ / 128), 256>>>(SCp, nullptr, out_W, out_b, nullptr,
                                                nullptr, rnext, C_, TNF);
        unsigned* tmp = rprev; rprev = rnext; rnext = tmp;
    }

    // out = (s*q_un*v) @ proj_W + proj_b   (16384x1024x1024)
    gemm_tc<128, 32, 64, MODE_PROJ>
        <<<dim3(C_ / 128, M_ / 128), 256>>>(qp, vp, proj_W, proj_b, out,
                                            rprev, nullptr, C_, 1024);
}

// round 3
// speedup vs baseline: 6.5042x; 1.4552x over previous
#include <cuda_runtime.h>
#include <math.h>
#include <stdint.h>

#define B_  8
#define T_  2048
#define C_  1024
#define NF_ 64
#define M_  (B_*T_)      /* 16384 */
#define TNF 128

// ---------------- scratch (device globals) ----------------
__device__ float    g_q[(size_t)M_ * C_];      // 64 MB, tf32-rounded, unnormalized
__device__ float    g_v[(size_t)M_ * C_];      // 64 MB, fp32
__device__ float    g_A[(size_t)M_ * C_];      // 64 MB: x_tf32, later (q*v*s)_tf32
__device__ float    g_G[(size_t)M_ * TNF];     // fp32
__device__ float    g_SC[(size_t)M_ * TNF];    // tf32-rounded
__device__ float    g_Wcat[C_ * TNF];          // tf32
__device__ float    g_attnW[C_ * 2 * C_];      // tf32
__device__ float    g_projW[C_ * C_];          // tf32
__device__ float    g_outW[TNF * C_];          // tf32
__device__ float    g_idG[NF_];
__device__ unsigned g_rm[2][M_];

enum { MODE_SPLIT = 0, MODE_PLAIN = 1, MODE_SCAN = 2, MODE_PROJ = 3 };

__device__ __forceinline__ uint32_t f2tf(float f) {
    uint32_t u; asm("cvt.rna.tf32.f32 %0, %1;" : "=r"(u) : "f"(f)); return u;
}
__device__ __forceinline__ float f2tff(float f) { return __uint_as_float(f2tf(f)); }
__device__ __forceinline__ void mma8(float* c, const uint32_t* a, const uint32_t* b) {
    asm volatile(
        "mma.sync.aligned.m16n8k8.row.col.f32.tf32.tf32.f32 "
        "{%0,%1,%2,%3},{%4,%5,%6,%7},{%8,%9},{%0,%1,%2,%3};\n"
        : "+f"(c[0]), "+f"(c[1]), "+f"(c[2]), "+f"(c[3])
        : "r"(a[0]), "r"(a[1]), "r"(a[2]), "r"(a[3]), "r"(b[0]), "r"(b[1]));
}
__device__ __forceinline__ void cpa16(uint32_t dst, const void* src) {
    asm volatile("cp.async.cg.shared.global [%0], [%1], 16;\n" :: "r"(dst), "l"(src));
}

// ---------------- pipelined tf32 tensor-core GEMM ----------------
// BN=128, BK=32. 256 threads = 8 warps. All operands pre-rounded to tf32.
template<int BM, int WM, int WN, int MODE>
__global__ __launch_bounds__(256, 2)
void gemm_tc(const float* __restrict__ A, const float* __restrict__ Bm,
             const float* __restrict__ bias, float* __restrict__ Cmat,
             unsigned* __restrict__ rmw, int N, int K)
{
    constexpr int BN = 128, BK = 32;
    constexpr int WARPS_N = BN / WN;
    constexpr int MT = WM / 16, NT = WN / 8;
    constexpr int ASZ = BM * 36;          // A stage: stride 36 (conflict-free frags)
    constexpr int BSZ = BK * 128;         // B stage: stride 128 + XOR swizzle

    extern __shared__ float sm[];
    const uint32_t smbase = (uint32_t)__cvta_generic_to_shared(sm);

    const int tid  = threadIdx.x;
    const int bm   = blockIdx.y * BM;
    const int bn   = blockIdx.x * BN;
    const int warp = tid >> 5, lane = tid & 31;
    const int grp  = lane >> 2, tig = lane & 3;
    const int wm   = warp / WARPS_N, wn = warp % WARPS_N;

    float acc[MT][NT][4];
#pragma unroll
    for (int i = 0; i < MT; i++)
#pragma unroll
        for (int j = 0; j < NT; j++)
#pragma unroll
            for (int r = 0; r < 4; r++) acc[i][j][r] = 0.f;

    // loaders
    const int lr = tid >> 3, lc = (tid & 7) * 4;           // A
    const int kr = tid >> 5;                               // B: k-row 0..7 (+8i)
    const int kchunk = tid & 31;
    const int kphys  = (kchunk ^ ((kr & 3) << 1)) * 4;     // swizzled float col

    auto ldA = [&](int st, int k0) {
#pragma unroll
        for (int i = 0; i < BM / 32; i++) {
            uint32_t d = smbase + (uint32_t)(st * ASZ + (lr + 32 * i) * 36 + lc) * 4u;
            cpa16(d, &A[(size_t)(bm + lr + 32 * i) * K + k0 + lc]);
        }
    };
    auto ldB = [&](int st, int k0) {
#pragma unroll
        for (int i = 0; i < 4; i++) {
            uint32_t d = smbase + (uint32_t)(2 * ASZ + st * BSZ + (kr + 8 * i) * 128 + kphys) * 4u;
            cpa16(d, &Bm[(size_t)(k0 + kr + 8 * i) * N + bn + kchunk * 4]);
        }
    };

    ldA(0, 0); ldB(0, 0);
    asm volatile("cp.async.commit_group;\n");

    const int nk = K / BK;
    for (int it = 0; it < nk; it++) {
        const int st = it & 1;
        if (it + 1 < nk) {
            ldA(st ^ 1, (it + 1) * BK);
            ldB(st ^ 1, (it + 1) * BK);
            asm volatile("cp.async.commit_group;\n");
            asm volatile("cp.async.wait_group 1;\n");
        } else {
            asm volatile("cp.async.wait_group 0;\n");
        }
        __syncthreads();

        const uint32_t* As32 = (const uint32_t*)sm + st * ASZ;
        const uint32_t* Bs32 = (const uint32_t*)sm + 2 * ASZ + st * BSZ;

#pragma unroll
        for (int ks = 0; ks < 4; ks++) {
            const int kk = ks * 8;
            uint32_t af[MT][4], bf[NT][2];
#pragma unroll
            for (int mt = 0; mt < MT; mt++) {
                int r = wm * WM + mt * 16 + grp;
                af[mt][0] = As32[r * 36 + kk + tig];
                af[mt][1] = As32[(r + 8) * 36 + kk + tig];
                af[mt][2] = As32[r * 36 + kk + tig + 4];
                af[mt][3] = As32[(r + 8) * 36 + kk + tig + 4];
            }
#pragma unroll
            for (int nt = 0; nt < NT; nt++) {
                int c = wn * WN + nt * 8 + grp;
                int p = (((c >> 2) ^ (tig << 1)) << 2) | (c & 3);
                bf[nt][0] = Bs32[(kk + tig) * 128 + p];
                bf[nt][1] = Bs32[(kk + tig + 4) * 128 + p];
            }
#pragma unroll
            for (int mt = 0; mt < MT; mt++)
#pragma unroll
                for (int nt = 0; nt < NT; nt++)
                    mma8(acc[mt][nt], af[mt], bf[nt]);
        }
        __syncthreads();
    }

    // ---------------- epilogue ----------------
#pragma unroll
    for (int mt = 0; mt < MT; mt++) {
        int row0 = bm + wm * WM + mt * 16 + grp;
        float mx0 = 0.f, mx1 = 0.f;
#pragma unroll
        for (int nt = 0; nt < NT; nt++) {
            int col = bn + wn * WN + nt * 8 + tig * 2;
            float v0 = acc[mt][nt][0], v1 = acc[mt][nt][1];
            float v2 = acc[mt][nt][2], v3 = acc[mt][nt][3];
            if (MODE != MODE_PLAIN) {
                float b0 = bias[col], b1 = bias[col + 1];
                v0 += b0; v1 += b1; v2 += b0; v3 += b1;
            }
            if (MODE == MODE_SPLIT) {
                if (col < C_) {   // q: tf32-rounded (GEMM operand downstream)
                    *(float2*)&g_q[(size_t)row0 * C_ + col]       = make_float2(f2tff(v0), f2tff(v1));
                    *(float2*)&g_q[(size_t)(row0 + 8) * C_ + col] = make_float2(f2tff(v2), f2tff(v3));
                } else {          // v: full fp32
                    *(float2*)&g_v[(size_t)row0 * C_ + col - C_]       = make_float2(v0, v1);
                    *(float2*)&g_v[(size_t)(row0 + 8) * C_ + col - C_] = make_float2(v2, v3);
                }
            } else if (MODE == MODE_SCAN) {
                mx0 = fmaxf(mx0, fmaxf(fabsf(v0), fabsf(v1)));
                mx1 = fmaxf(mx1, fmaxf(fabsf(v2), fabsf(v3)));
                *(float2*)&g_q[(size_t)row0 * C_ + col]       = make_float2(f2tff(v0), f2tff(v1));
                *(float2*)&g_q[(size_t)(row0 + 8) * C_ + col] = make_float2(f2tff(v2), f2tff(v3));
            } else {
                *(float2*)&Cmat[(size_t)row0 * N + col]       = make_float2(v0, v1);
                *(float2*)&Cmat[(size_t)(row0 + 8) * N + col] = make_float2(v2, v3);
            }
        }
        if (MODE == MODE_SCAN) {
#pragma unroll
            for (int off = 1; off < 4; off <<= 1) {
                mx0 = fmaxf(mx0, __shfl_xor_sync(0xffffffffu, mx0, off));
                mx1 = fmaxf(mx1, __shfl_xor_sync(0xffffffffu, mx1, off));
            }
            if (tig == 0) {
                atomicMax(&rmw[row0],     __float_as_uint(mx0));
                atomicMax(&rmw[row0 + 8], __float_as_uint(mx1));
            }
        }
    }
}

// ---------------- small kernels ----------------
__global__ void cvt_k(const float* __restrict__ src, float* __restrict__ dst)
{
    size_t i = ((size_t)blockIdx.x * 256 + threadIdx.x) * 4;
    float4 v = *(const float4*)&src[i];
    v.x = f2tff(v.x); v.y = f2tff(v.y); v.z = f2tff(v.z); v.w = f2tff(v.w);
    *(float4*)&dst[i] = v;
}

__global__ void pack_wcat_k(const float* __restrict__ freqW)
{
    int idx = blockIdx.x * 256 + threadIdx.x;      // < 1024*128
    int k = idx >> 7, j = idx & 127;
    float w = (j < 64) ? freqW[k * 64 + j] : freqW[(k + 1024) * 64 + (j - 64)];
    g_Wcat[idx] = f2tff(w);
}

__global__ void idg_k(const float* __restrict__ freqW, const float* __restrict__ identity)
{
    int j = threadIdx.x;   // 64 threads
    float s = 0.f;
    for (int k = 0; k < 1024; k++) s = fmaf(identity[k], freqW[k * 64 + j], s);
    g_idG[j] = s;
}

__global__ void init_rm_k()
{
    g_rm[0][blockIdx.x * 256 + threadIdx.x] = __float_as_uint(1.0f - 1e-6f);
}

// shift + per-row scale + sin/cos -> g_SC (tf32); zeroes rmnext
__global__ __launch_bounds__(256)
void sc_k(const float* __restrict__ freq_b, int n,
          const unsigned* __restrict__ rmprev, unsigned* __restrict__ rmnext)
{
    int idx = blockIdx.x * 256 + threadIdx.x;      // < M*64
    int row = idx >> 6, j = idx & 63;
    if (j == 0) rmnext[row] = 0u;
    int t = row & (T_ - 1);
    float sown = 1.f / (__uint_as_float(rmprev[row]) + 1e-6f);
    float g2 = g_G[(size_t)row * TNF + 64 + j] * sown;
    float g1;
    if (t >= n) {
        float sp = 1.f / (__uint_as_float(rmprev[row - n]) + 1e-6f);
        g1 = g_G[(size_t)(row - n) * TNF + j] * sp;
    } else {
        g1 = g_idG[j];
    }
    float f = g1 + g2 + freq_b[j];
    float s, c;
    sincosf(f, &s, &c);
    g_SC[(size_t)row * TNF + j]      = f2tff(s);
    g_SC[(size_t)row * TNF + 64 + j] = f2tff(c);
}

// A_proj = tf32(q * v * s)  -> g_A
__global__ __launch_bounds__(256)
void aproj_k(const unsigned* __restrict__ rm)
{
    size_t i = ((size_t)blockIdx.x * 256 + threadIdx.x) * 4;
    int row = (int)(i >> 10);
    float s = 1.f / (__uint_as_float(rm[row]) + 1e-6f);
    float4 q = *(const float4*)&g_q[i];
    float4 v = *(const float4*)&g_v[i];
    q.x = f2tff(q.x * v.x * s); q.y = f2tff(q.y * v.y * s);
    q.z = f2tff(q.z * v.z * s); q.w = f2tff(q.w * v.w * s);
    *(float4*)&g_A[i] = q;
}

// ---------------- launch ----------------
extern "C" void kernel_launch(void* const* d_in, const int* in_sizes, int n_in,
                              void* d_out, int out_size)
{
    (void)in_sizes; (void)n_in; (void)out_size;
    const float* x        = (const float*)d_in[0];
    const float* attn_W   = (const float*)d_in[1];
    const float* attn_b   = (const float*)d_in[2];
    const float* freq_W   = (const float*)d_in[3];
    const float* freq_b   = (const float*)d_in[4];
    const float* out_W    = (const float*)d_in[5];
    const float* out_b    = (const float*)d_in[6];
    const float* proj_W   = (const float*)d_in[7];
    const float* proj_b   = (const float*)d_in[8];
    const float* identity = (const float*)d_in[9];
    float* out = (float*)d_out;

    float *qp, *Ap, *Gp, *SCp, *Wcatp, *aWp, *pWp, *oWp;
    unsigned* rmp;
    cudaGetSymbolAddress((void**)&qp,    g_q);
    cudaGetSymbolAddress((void**)&Ap,    g_A);
    cudaGetSymbolAddress((void**)&Gp,    g_G);
    cudaGetSymbolAddress((void**)&SCp,   g_SC);
    cudaGetSymbolAddress((void**)&Wcatp, g_Wcat);
    cudaGetSymbolAddress((void**)&aWp,   g_attnW);
    cudaGetSymbolAddress((void**)&pWp,   g_projW);
    cudaGetSymbolAddress((void**)&oWp,   g_outW);
    cudaGetSymbolAddress((void**)&rmp,   g_rm);

    constexpr int SMEM128 = 2 * (128 * 36 + 32 * 128) * 4;   // 69632
    constexpr int SMEM64  = 2 * (64 * 36 + 32 * 128) * 4;    // 51200
    cudaFuncSetAttribute(gemm_tc<128, 32, 64, MODE_SPLIT>,
                         cudaFuncAttributeMaxDynamicSharedMemorySize, SMEM128);
    cudaFuncSetAttribute(gemm_tc<64, 32, 32, MODE_PLAIN>,
                         cudaFuncAttributeMaxDynamicSharedMemorySize, SMEM64);
    cudaFuncSetAttribute(gemm_tc<128, 32, 64, MODE_SCAN>,
                         cudaFuncAttributeMaxDynamicSharedMemorySize, SMEM128);
    cudaFuncSetAttribute(gemm_tc<128, 32, 64, MODE_PROJ>,
                         cudaFuncAttributeMaxDynamicSharedMemorySize, SMEM128);

    // pre-round weights/activations to tf32
    cvt_k<<<(M_ * C_) / 1024, 256>>>(x, Ap);
    cvt_k<<<(C_ * 2 * C_) / 1024, 256>>>(attn_W, aWp);
    cvt_k<<<(C_ * C_) / 1024, 256>>>(proj_W, pWp);
    cvt_k<<<(TNF * C_) / 1024, 256>>>(out_W, oWp);
    pack_wcat_k<<<512, 256>>>(freq_W);
    idg_k<<<1, 64>>>(freq_W, identity);
    init_rm_k<<<M_ / 256, 256>>>();

    // qv = x @ attn_W + attn_b -> g_q (tf32) / g_v (fp32)
    gemm_tc<128, 32, 64, MODE_SPLIT>
        <<<dim3(2048 / 128, M_ / 128), 256, SMEM128>>>(Ap, aWp, attn_b, nullptr,
                                                       nullptr, 2048, 1024);

    unsigned* rprev = rmp;
    unsigned* rnext = rmp + M_;

    for (int n = 1; n < T_; n <<= 1) {
        gemm_tc<64, 32, 32, MODE_PLAIN>
            <<<dim3(1, M_ / 64), 256, SMEM64>>>(qp, Wcatp, nullptr, Gp,
                                                nullptr, TNF, 1024);
        sc_k<<<(M_ * 64) / 256, 256>>>(freq_b, n, rprev, rnext);
        gemm_tc<128, 32, 64, MODE_SCAN>
            <<<dim3(C_ / 128, M_ / 128), 256, SMEM128>>>(SCp, oWp, out_b, nullptr,
                                                         rnext, C_, TNF);
        unsigned* tmp = rprev; rprev = rnext; rnext = tmp;
    }

    // out = (q*v*s) @ proj_W + proj_b
    aproj_k<<<(M_ * C_) / 1024, 256>>>(rprev);
    gemm_tc<128, 32, 64, MODE_PROJ>
        <<<dim3(C_ / 128, M_ / 128), 256, SMEM128>>>(Ap, pWp, proj_b, out,
                                                     nullptr, C_, 1024);
}

// round 4
// speedup vs baseline: 9.1750x; 1.4106x over previous
#include <cuda_runtime.h>
#include <math.h>
#include <stdint.h>

#define B_  8
#define T_  2048
#define C_  1024
#define NF_ 64
#define M_  (B_*T_)      /* 16384 */
#define TNF 128

// ---------------- scratch (device globals) ----------------
__device__ float    g_q[(size_t)M_ * C_];      // final q only (tf32)
__device__ float    g_v[(size_t)M_ * C_];      // fp32
__device__ float    g_A[(size_t)M_ * C_];      // x_tf32, later (q*v*s)_tf32
__device__ float    g_G[(size_t)M_ * TNF];     // fp32, loop state
__device__ float    g_SC[(size_t)M_ * TNF];    // tf32
__device__ float    g_Wcat[C_ * TNF];          // fp32 exact [Wtop|Wbot]
__device__ float    g_Wb1[C_ * 1152];          // tf32 [attn_W_v | Wq@Wcat]
__device__ float    g_Wb2[TNF * 1152];         // tf32 [out_W | out_W@Wcat]
__device__ float    g_projW[C_ * C_];          // tf32
__device__ float    g_bias1[1152];             // [attn_b_v | attn_b_q@Wcat]
__device__ float    g_bias2[1152];             // [out_b | out_b@Wcat]
__device__ float    g_idG[NF_];
__device__ unsigned g_rm[2][M_];

enum { MODE_SPLIT = 0, MODE_LOOP = 1, MODE_SCAN = 2, MODE_PROJ = 3 };

__device__ __forceinline__ uint32_t f2tf(float f) {
    uint32_t u; asm("cvt.rna.tf32.f32 %0, %1;" : "=r"(u) : "f"(f)); return u;
}
__device__ __forceinline__ float f2tff(float f) { return __uint_as_float(f2tf(f)); }
__device__ __forceinline__ void mma8(float* c, const uint32_t* a, const uint32_t* b) {
    asm volatile(
        "mma.sync.aligned.m16n8k8.row.col.f32.tf32.tf32.f32 "
        "{%0,%1,%2,%3},{%4,%5,%6,%7},{%8,%9},{%0,%1,%2,%3};\n"
        : "+f"(c[0]), "+f"(c[1]), "+f"(c[2]), "+f"(c[3])
        : "r"(a[0]), "r"(a[1]), "r"(a[2]), "r"(a[3]), "r"(b[0]), "r"(b[1]));
}
__device__ __forceinline__ void cpa16(uint32_t dst, const void* src) {
    asm volatile("cp.async.cg.shared.global [%0], [%1], 16;\n" :: "r"(dst), "l"(src));
}

// ---------------- pipelined tf32 tensor-core GEMM (BM=128, BN=128, BK=32) ----------------
template<int MODE>
__global__ __launch_bounds__(256, 2)
void gemm_tc(const float* __restrict__ A, const float* __restrict__ Bm,
             const float* __restrict__ bias, float* __restrict__ Cmat,
             unsigned* __restrict__ rmw, int N, int ldb, int K)
{
    constexpr int BM = 128, WM = 32, WN = 64, BK = 32;
    constexpr int WARPS_N = 2;
    constexpr int MT = WM / 16, NT = WN / 8;
    constexpr int ASZ = BM * 36;
    constexpr int BSZ = BK * 128;

    extern __shared__ float sm[];
    const uint32_t smbase = (uint32_t)__cvta_generic_to_shared(sm);

    const int tid  = threadIdx.x;
    const int bm   = blockIdx.y * BM;
    const int bn   = blockIdx.x * 128;
    const int warp = tid >> 5, lane = tid & 31;
    const int grp  = lane >> 2, tig = lane & 3;
    const int wm   = warp / WARPS_N, wn = warp % WARPS_N;

    float acc[MT][NT][4];
#pragma unroll
    for (int i = 0; i < MT; i++)
#pragma unroll
        for (int j = 0; j < NT; j++)
#pragma unroll
            for (int r = 0; r < 4; r++) acc[i][j][r] = 0.f;

    const int lr = tid >> 3, lc = (tid & 7) * 4;
    const int kr = tid >> 5;
    const int kchunk = tid & 31;
    const int kphys  = (kchunk ^ ((kr & 3) << 1)) * 4;

    auto ldA = [&](int st, int k0) {
#pragma unroll
        for (int i = 0; i < BM / 32; i++) {
            uint32_t d = smbase + (uint32_t)(st * ASZ + (lr + 32 * i) * 36 + lc) * 4u;
            cpa16(d, &A[(size_t)(bm + lr + 32 * i) * K + k0 + lc]);
        }
    };
    auto ldB = [&](int st, int k0) {
#pragma unroll
        for (int i = 0; i < 4; i++) {
            uint32_t d = smbase + (uint32_t)(2 * ASZ + st * BSZ + (kr + 8 * i) * 128 + kphys) * 4u;
            cpa16(d, &Bm[(size_t)(k0 + kr + 8 * i) * ldb + bn + kchunk * 4]);
        }
    };

    ldA(0, 0); ldB(0, 0);
    asm volatile("cp.async.commit_group;\n");

    const int nk = K / BK;
    for (int it = 0; it < nk; it++) {
        const int st = it & 1;
        if (it + 1 < nk) {
            ldA(st ^ 1, (it + 1) * BK);
            ldB(st ^ 1, (it + 1) * BK);
            asm volatile("cp.async.commit_group;\n");
            asm volatile("cp.async.wait_group 1;\n");
        } else {
            asm volatile("cp.async.wait_group 0;\n");
        }
        __syncthreads();

        const uint32_t* As32 = (const uint32_t*)sm + st * ASZ;
        const uint32_t* Bs32 = (const uint32_t*)sm + 2 * ASZ + st * BSZ;

#pragma unroll
        for (int ks = 0; ks < 4; ks++) {
            const int kk = ks * 8;
            uint32_t af[MT][4], bf[NT][2];
#pragma unroll
            for (int mt = 0; mt < MT; mt++) {
                int r = wm * WM + mt * 16 + grp;
                af[mt][0] = As32[r * 36 + kk + tig];
                af[mt][1] = As32[(r + 8) * 36 + kk + tig];
                af[mt][2] = As32[r * 36 + kk + tig + 4];
                af[mt][3] = As32[(r + 8) * 36 + kk + tig + 4];
            }
#pragma unroll
            for (int nt = 0; nt < NT; nt++) {
                int c = wn * WN + nt * 8 + grp;
                int p = (((c >> 2) ^ (tig << 1)) << 2) | (c & 3);
                bf[nt][0] = Bs32[(kk + tig) * 128 + p];
                bf[nt][1] = Bs32[(kk + tig + 4) * 128 + p];
            }
#pragma unroll
            for (int mt = 0; mt < MT; mt++)
#pragma unroll
                for (int nt = 0; nt < NT; nt++)
                    mma8(acc[mt][nt], af[mt], bf[nt]);
        }
        __syncthreads();
    }

    // ---------------- epilogue ----------------
#pragma unroll
    for (int mt = 0; mt < MT; mt++) {
        int row0 = bm + wm * WM + mt * 16 + grp;
        float mx0 = 0.f, mx1 = 0.f;
#pragma unroll
        for (int nt = 0; nt < NT; nt++) {
            int col = bn + wn * WN + nt * 8 + tig * 2;
            float b0 = bias[col], b1 = bias[col + 1];
            float v0 = acc[mt][nt][0] + b0, v1 = acc[mt][nt][1] + b1;
            float v2 = acc[mt][nt][2] + b0, v3 = acc[mt][nt][3] + b1;
            if (MODE == MODE_SPLIT) {
                if (col < C_) {
                    *(float2*)&g_v[(size_t)row0 * C_ + col]       = make_float2(v0, v1);
                    *(float2*)&g_v[(size_t)(row0 + 8) * C_ + col] = make_float2(v2, v3);
                } else {
                    int lcol = col - C_;
                    *(float2*)&g_G[(size_t)row0 * TNF + lcol]       = make_float2(v0, v1);
                    *(float2*)&g_G[(size_t)(row0 + 8) * TNF + lcol] = make_float2(v2, v3);
                }
            } else if (MODE == MODE_LOOP) {
                if (col < C_) {
                    mx0 = fmaxf(mx0, fmaxf(fabsf(v0), fabsf(v1)));
                    mx1 = fmaxf(mx1, fmaxf(fabsf(v2), fabsf(v3)));
                } else {
                    int lcol = col - C_;
                    *(float2*)&g_G[(size_t)row0 * TNF + lcol]       = make_float2(v0, v1);
                    *(float2*)&g_G[(size_t)(row0 + 8) * TNF + lcol] = make_float2(v2, v3);
                }
            } else if (MODE == MODE_SCAN) {
                mx0 = fmaxf(mx0, fmaxf(fabsf(v0), fabsf(v1)));
                mx1 = fmaxf(mx1, fmaxf(fabsf(v2), fabsf(v3)));
                *(float2*)&g_q[(size_t)row0 * C_ + col]       = make_float2(f2tff(v0), f2tff(v1));
                *(float2*)&g_q[(size_t)(row0 + 8) * C_ + col] = make_float2(f2tff(v2), f2tff(v3));
            } else {
                *(float2*)&Cmat[(size_t)row0 * N + col]       = make_float2(v0, v1);
                *(float2*)&Cmat[(size_t)(row0 + 8) * N + col] = make_float2(v2, v3);
            }
        }
        if (MODE == MODE_SCAN || (MODE == MODE_LOOP && bn < C_)) {
#pragma unroll
            for (int off = 1; off < 4; off <<= 1) {
                mx0 = fmaxf(mx0, __shfl_xor_sync(0xffffffffu, mx0, off));
                mx1 = fmaxf(mx1, __shfl_xor_sync(0xffffffffu, mx1, off));
            }
            if (tig == 0) {
                atomicMax(&rmw[row0],     __float_as_uint(mx0));
                atomicMax(&rmw[row0 + 8], __float_as_uint(mx1));
            }
        }
    }
}

// ---------------- pre-pass kernels ----------------
__global__ void cvt_k(const float* __restrict__ src, float* __restrict__ dst)
{
    size_t i = ((size_t)blockIdx.x * 256 + threadIdx.x) * 4;
    float4 v = *(const float4*)&src[i];
    v.x = f2tff(v.x); v.y = f2tff(v.y); v.z = f2tff(v.z); v.w = f2tff(v.w);
    *(float4*)&dst[i] = v;
}

__global__ void pack_wcat_k(const float* __restrict__ freqW)
{
    int idx = blockIdx.x * 256 + threadIdx.x;      // < 1024*128
    int k = idx >> 7, j = idx & 127;
    g_Wcat[idx] = (j < 64) ? freqW[k * 64 + j] : freqW[(k + 1024) * 64 + (j - 64)];
}

__global__ void wb1_k(const float* __restrict__ attnW)
{
    int i = blockIdx.y * 2 + (threadIdx.x >> 7);
    int c = blockIdx.x * 128 + (threadIdx.x & 127);
    float w;
    if (c < C_) {
        w = attnW[(size_t)i * 2048 + C_ + c];               // v-columns
    } else {
        int j = c - C_;                                     // W1 = Wq @ Wcat
        float s = 0.f;
        for (int k = 0; k < C_; k++)
            s = fmaf(attnW[(size_t)i * 2048 + k], g_Wcat[k * TNF + j], s);
        w = s;
    }
    g_Wb1[i * 1152 + c] = f2tff(w);
}

__global__ void wb2_k(const float* __restrict__ outW)
{
    int i = blockIdx.y * 2 + (threadIdx.x >> 7);
    int c = blockIdx.x * 128 + (threadIdx.x & 127);
    float w;
    if (c < C_) {
        w = outW[(size_t)i * C_ + c];
    } else {
        int j = c - C_;                                     // W2 = out_W @ Wcat
        float s = 0.f;
        for (int k = 0; k < C_; k++)
            s = fmaf(outW[(size_t)i * C_ + k], g_Wcat[k * TNF + j], s);
        w = s;
    }
    g_Wb2[i * 1152 + c] = f2tff(w);
}

__global__ void bias1_k(const float* __restrict__ attn_b)
{
    int c = blockIdx.x * 256 + threadIdx.x;
    if (c >= 1152) return;
    if (c < C_) { g_bias1[c] = attn_b[C_ + c]; return; }
    int j = c - C_;
    float s = 0.f;
    for (int k = 0; k < C_; k++) s = fmaf(attn_b[k], g_Wcat[k * TNF + j], s);
    g_bias1[c] = s;
}

__global__ void bias2_k(const float* __restrict__ out_b)
{
    int c = blockIdx.x * 256 + threadIdx.x;
    if (c >= 1152) return;
    if (c < C_) { g_bias2[c] = out_b[c]; return; }
    int j = c - C_;
    float s = 0.f;
    for (int k = 0; k < C_; k++) s = fmaf(out_b[k], g_Wcat[k * TNF + j], s);
    g_bias2[c] = s;
}

__global__ void idg_k(const float* __restrict__ freqW, const float* __restrict__ identity)
{
    int j = threadIdx.x;   // 64
    float s = 0.f;
    for (int k = 0; k < C_; k++) s = fmaf(identity[k], freqW[k * 64 + j], s);
    g_idG[j] = s;
}

__global__ void init_rm_k()
{
    g_rm[0][blockIdx.x * 256 + threadIdx.x] = __float_as_uint(1.0f - 1e-6f);
}

// shift + scale + sincos -> g_SC (tf32); zero rmnext. 4 j's per thread.
__global__ __launch_bounds__(256)
void sc_k(const float* __restrict__ freq_b, int n,
          const unsigned* __restrict__ rmprev, unsigned* __restrict__ rmnext)
{
    int idx = blockIdx.x * 256 + threadIdx.x;      // < M*16
    int row = idx >> 4, jq = (idx & 15) * 4;
    if (jq == 0) rmnext[row] = 0u;
    int t = row & (T_ - 1);
    float sown = 1.f / (__uint_as_float(rmprev[row]) + 1e-6f);
    float4 g2 = *(const float4*)&g_G[(size_t)row * TNF + 64 + jq];
    float4 g1;
    if (t >= n) {
        float sp = 1.f / (__uint_as_float(rmprev[row - n]) + 1e-6f);
        g1 = *(const float4*)&g_G[(size_t)(row - n) * TNF + jq];
        g1.x *= sp; g1.y *= sp; g1.z *= sp; g1.w *= sp;
    } else {
        g1 = *(const float4*)&g_idG[jq];
    }
    float4 fb = *(const float4*)&freq_b[jq];
    float f0 = g1.x + g2.x * sown + fb.x;
    float f1 = g1.y + g2.y * sown + fb.y;
    float f2 = g1.z + g2.z * sown + fb.z;
    float f3 = g1.w + g2.w * sown + fb.w;
    float s0, c0, s1, c1, s2, c2, s3, c3;
    sincosf(f0, &s0, &c0); sincosf(f1, &s1, &c1);
    sincosf(f2, &s2, &c2); sincosf(f3, &s3, &c3);
    *(float4*)&g_SC[(size_t)row * TNF + jq] =
        make_float4(f2tff(s0), f2tff(s1), f2tff(s2), f2tff(s3));
    *(float4*)&g_SC[(size_t)row * TNF + 64 + jq] =
        make_float4(f2tff(c0), f2tff(c1), f2tff(c2), f2tff(c3));
}

// A_proj = tf32(q * v * s)
__global__ __launch_bounds__(256)
void aproj_k(const unsigned* __restrict__ rm)
{
    size_t i = ((size_t)blockIdx.x * 256 + threadIdx.x) * 4;
    int row = (int)(i >> 10);
    float s = 1.f / (__uint_as_float(rm[row]) + 1e-6f);
    float4 q = *(const float4*)&g_q[i];
    float4 v = *(const float4*)&g_v[i];
    q.x = f2tff(q.x * v.x * s); q.y = f2tff(q.y * v.y * s);
    q.z = f2tff(q.z * v.z * s); q.w = f2tff(q.w * v.w * s);
    *(float4*)&g_A[i] = q;
}

// ---------------- launch ----------------
extern "C" void kernel_launch(void* const* d_in, const int* in_sizes, int n_in,
                              void* d_out, int out_size)
{
    (void)in_sizes; (void)n_in; (void)out_size;
    const float* x        = (const float*)d_in[0];
    const float* attn_W   = (const float*)d_in[1];
    const float* attn_b   = (const float*)d_in[2];
    const float* freq_W   = (const float*)d_in[3];
    const float* freq_b   = (const float*)d_in[4];
    const float* out_W    = (const float*)d_in[5];
    const float* out_b    = (const float*)d_in[6];
    const float* proj_W   = (const float*)d_in[7];
    const float* proj_b   = (const float*)d_in[8];
    const float* identity = (const float*)d_in[9];
    float* out = (float*)d_out;

    float *Ap, *SCp, *Wb1p, *Wb2p, *pWp, *b1p, *b2p;
    unsigned* rmp;
    cudaGetSymbolAddress((void**)&Ap,   g_A);
    cudaGetSymbolAddress((void**)&SCp,  g_SC);
    cudaGetSymbolAddress((void**)&Wb1p, g_Wb1);
    cudaGetSymbolAddress((void**)&Wb2p, g_Wb2);
    cudaGetSymbolAddress((void**)&pWp,  g_projW);
    cudaGetSymbolAddress((void**)&b1p,  g_bias1);
    cudaGetSymbolAddress((void**)&b2p,  g_bias2);
    cudaGetSymbolAddress((void**)&rmp,  g_rm);

    constexpr int SMEM = 2 * (128 * 36 + 32 * 128) * 4;   // 69632
    cudaFuncSetAttribute(gemm_tc<MODE_SPLIT>, cudaFuncAttributeMaxDynamicSharedMemorySize, SMEM);
    cudaFuncSetAttribute(gemm_tc<MODE_LOOP>,  cudaFuncAttributeMaxDynamicSharedMemorySize, SMEM);
    cudaFuncSetAttribute(gemm_tc<MODE_SCAN>,  cudaFuncAttributeMaxDynamicSharedMemorySize, SMEM);
    cudaFuncSetAttribute(gemm_tc<MODE_PROJ>,  cudaFuncAttributeMaxDynamicSharedMemorySize, SMEM);

    // pre-pass
    pack_wcat_k<<<512, 256>>>(freq_W);
    cvt_k<<<(M_ * C_) / 1024, 256>>>(x, Ap);
    cvt_k<<<(C_ * C_) / 1024, 256>>>(proj_W, pWp);
    wb1_k<<<dim3(9, 512), 256>>>(attn_W);
    wb2_k<<<dim3(9, 64), 256>>>(out_W);
    bias1_k<<<5, 256>>>(attn_b);
    bias2_k<<<5, 256>>>(out_b);
    idg_k<<<1, 64>>>(freq_W, identity);
    init_rm_k<<<M_ / 256, 256>>>();

    // split: [v | G0] = x @ [Wv | Wq@Wcat] + bias1
    gemm_tc<MODE_SPLIT>
        <<<dim3(9, M_ / 128), 256, SMEM>>>(Ap, Wb1p, b1p, nullptr, nullptr,
                                           1152, 1152, 1024);

    unsigned* rprev = rmp;
    unsigned* rnext = rmp + M_;

    for (int n = 1; n < T_; n <<= 1) {
        sc_k<<<(M_ * 16) / 256, 256>>>(freq_b, n, rprev, rnext);
        if (n < 1024) {
            gemm_tc<MODE_LOOP>
                <<<dim3(9, M_ / 128), 256, SMEM>>>(SCp, Wb2p, b2p, nullptr, rnext,
                                                   1152, 1152, 128);
        } else {
            gemm_tc<MODE_SCAN>
                <<<dim3(8, M_ / 128), 256, SMEM>>>(SCp, Wb2p, b2p, nullptr, rnext,
                                                   1024, 1152, 128);
        }
        unsigned* tmp = rprev; rprev = rnext; rnext = tmp;
    }

    // out = (q*v*s) @ proj_W + proj_b
    aproj_k<<<(M_ * C_) / 1024, 256>>>(rprev);
    gemm_tc<MODE_PROJ>
        <<<dim3(8, M_ / 128), 256, SMEM>>>(Ap, pWp, proj_b, out, nullptr,
                                           1024, 1024, 1024);
}